// round 11
// baseline (speedup 1.0000x reference)
#include <cuda_runtime.h>
#include <stdint.h>
#include <math.h>

#define NB 64
#define NH 1024
#define NV 32000
#define NT 31
#define NBLK 125   // gemmF n-slices (32000/256)

// -------- device scratch --------
__device__ float g_W1p[512 * 4096];     // gate-interleaved Wx1
__device__ float g_W2p[1024 * 4096];    // gate-interleaved Wx2+Wh2
__device__ float g_hs[(NT + 1) * NB * NH];  // h after encoder (hs[0]) and each decoder step
__device__ float g_c[NB * NH];
__device__ float4 g_pm[NT * NBLK * NB];    // per-block softmax partials (m,S,T)
__device__ float4 g_pa[NT * NBLK * NB];    // per-block argmax partials (best, idx, l)

__device__ __forceinline__ float negInf() { return __int_as_float(0xff800000); }

// ---- packed f32x2 FMA (sm_103a): two independent rn-FMAs per instruction ----
__device__ __forceinline__ unsigned long long pk2(float x) {
    unsigned long long r;
    asm("mov.b64 %0, {%1, %1};" : "=l"(r) : "f"(x));
    return r;
}
__device__ __forceinline__ void fma2(unsigned long long& c, unsigned long long a,
                                     unsigned long long b) {
    asm("fma.rn.f32x2 %0, %1, %2, %0;" : "+l"(c) : "l"(a), "l"(b));
}
__device__ __forceinline__ float lo32(unsigned long long v) {
    return __uint_as_float((unsigned)v);
}
__device__ __forceinline__ float hi32(unsigned long long v) {
    return __uint_as_float((unsigned)(v >> 32));
}

// exact JAX threefry2x32 (20 rounds)
__device__ __forceinline__ void tf2x32(uint32_t k0, uint32_t k1,
                                       uint32_t x0, uint32_t x1,
                                       uint32_t& o0, uint32_t& o1) {
    uint32_t k2 = k0 ^ k1 ^ 0x1BD11BDAu;
    x0 += k0; x1 += k1;
#define TFR(r) { x0 += x1; x1 = (x1 << (r)) | (x1 >> (32 - (r))); x1 ^= x0; }
    TFR(13) TFR(15) TFR(26) TFR(6)
    x0 += k1; x1 += k2 + 1u;
    TFR(17) TFR(29) TFR(16) TFR(24)
    x0 += k2; x1 += k0 + 2u;
    TFR(13) TFR(15) TFR(26) TFR(6)
    x0 += k0; x1 += k1 + 3u;
    TFR(17) TFR(29) TFR(16) TFR(24)
    x0 += k1; x1 += k2 + 4u;
    TFR(13) TFR(15) TFR(26) TFR(6)
    x0 += k2; x1 += k0 + 5u;
#undef TFR
    o0 = x0; o1 = x1;
}

__device__ __forceinline__ float u01(uint32_t b) {
    float f = __uint_as_float((b >> 9) | 0x3f800000u) - 1.0f;
    return fmaxf(f, 1.17549435e-38f);
}

// exact gumbel increment (bit-identical to R6..R10 formula)
__device__ __forceinline__ float exact_g(float u) {
    return (float)(-log(-log((double)u)));
}

__device__ __forceinline__ void softmerge(float& m, float& S, float& T,
                                          float m2, float S2, float T2) {
    if (S2 == 0.f) return;
    if (S == 0.f) { m = m2; S = S2; T = T2; return; }
    if (m2 > m) {
        float t;
        t = m; m = m2; m2 = t;
        t = S; S = S2; S2 = t;
        t = T; T = T2; T2 = t;
    }
    float e = expf(m2 - m);
    S += S2 * e;
    T += (T2 + (m2 - m) * S2) * e;
}

__global__ void k_init() {
    int i = blockIdx.x * blockDim.x + threadIdx.x;
    if (i < NB * NH) g_c[i] = 0.f;
}
__global__ void k_init2(float* __restrict__ out) {
    int i = blockIdx.x * blockDim.x + threadIdx.x;
    if (i < 3 * NB * 2 * NT) out[i] = 0.f;
}

// Gate-interleave permutation: Wp[k][4j+q] = W[k][q*1024+j]
__global__ void k_prep(const float* __restrict__ Wx1, const float* __restrict__ Wx2,
                       const float* __restrict__ Wh2) {
    int idx = blockIdx.x * blockDim.x + threadIdx.x;   // < 1024*4096
    int k = idx >> 12, col = idx & 4095;
    int j = col >> 2, q = col & 3;
    int src = (k << 12) + (q << 10) + j;
    g_W2p[idx] = Wx2[src] + Wh2[src];
    if (k < 512) g_W1p[idx] = Wx1[src];
}

// Fused gate GEMM + LSTM pointwise. Double-buffered smem (1 barrier/chunk) +
// depth-2 register prefetch. One cell per thread (aif, ago packed).
__global__ __launch_bounds__(256, 2) void gemmG(const float* __restrict__ A,
                                                const float* __restrict__ W,
                                                const float* __restrict__ bias,
                                                float* __restrict__ hout,
                                                int K) {
    __shared__ float As[2][16][64];
    __shared__ float Bs[2][16][16];
    const int tid = threadIdx.x;
    const int row = tid & 63;
    const int jj  = tid >> 6;              // 0..3
    const int j0  = blockIdx.x * 4;        // 4 j-states per block
    const int c0  = blockIdx.x * 16;       // 16 permuted cols per block
    const int ar = tid >> 2, ak = (tid & 3) * 4;
    const int bk = tid >> 2, bc = (tid & 3) * 4;   // B staging (tid < 64)
    const int NC = K / 16;

    unsigned long long aif = 0, ago = 0;

    // prolog: chunk0 -> buf0; chunk1 staged in regs
    float4 pa0 = *(const float4*)(A + ar * K + ak);
    float4 pa1 = *(const float4*)(A + ar * K + 16 + ak);
    float4 pb0, pb1;
    if (tid < 64) {
        pb0 = *(const float4*)(W + (size_t)bk * 4096 + c0 + bc);
        pb1 = *(const float4*)(W + (size_t)(16 + bk) * 4096 + c0 + bc);
    }
    As[0][ak + 0][ar] = pa0.x; As[0][ak + 1][ar] = pa0.y;
    As[0][ak + 2][ar] = pa0.z; As[0][ak + 3][ar] = pa0.w;
    if (tid < 64) *(float4*)&Bs[0][bk][bc] = pb0;
    __syncthreads();
    pa0 = pa1;
    if (tid < 64) pb0 = pb1;

    for (int c = 0; c < NC; c++) {
        int cur = c & 1;
        if (c + 2 < NC) {   // issue LDG for chunk c+2 (depth-2)
            pa1 = *(const float4*)(A + ar * K + (c + 2) * 16 + ak);
            if (tid < 64)
                pb1 = *(const float4*)(W + (size_t)((c + 2) * 16 + bk) * 4096 + c0 + bc);
        }
#pragma unroll
        for (int k = 0; k < 16; k++) {
            unsigned long long ap = pk2(As[cur][k][row]);
            ulonglong2 bA = *(const ulonglong2*)&Bs[cur][k][jj * 4];
            fma2(aif, ap, bA.x);
            fma2(ago, ap, bA.y);
        }
        if (c + 1 < NC) {   // store chunk c+1 (regs) -> other buffer
            As[cur ^ 1][ak + 0][ar] = pa0.x; As[cur ^ 1][ak + 1][ar] = pa0.y;
            As[cur ^ 1][ak + 2][ar] = pa0.z; As[cur ^ 1][ak + 3][ar] = pa0.w;
            if (tid < 64) *(float4*)&Bs[cur ^ 1][bk][bc] = pb0;
        }
        __syncthreads();
        pa0 = pa1;
        if (tid < 64) pb0 = pb1;
    }

    int j = j0 + jj;
    float zi = __fadd_rn(lo32(aif), bias[j]);
    float zf = __fadd_rn(hi32(aif), bias[1024 + j]);
    float zg = __fadd_rn(lo32(ago), bias[2048 + j]);
    float zo = __fadd_rn(hi32(ago), bias[3072 + j]);
    float si = 1.f / (1.f + expf(-zi));
    float sf = 1.f / (1.f + expf(-zf));
    float so = 1.f / (1.f + expf(-zo));
    int ci = row * NH + j;
    float cn = __fadd_rn(__fmul_rn(sf, g_c[ci]), __fmul_rn(si, zg));
    g_c[ci] = cn;
    hout[ci] = __fmul_rn(so, cn);
}

// ALL 31 steps' logits GEMM + softmax partials + gumbel sampling in one grid.
// blockIdx.x = t (31), blockIdx.y = n-slice (125): same-wave blocks share Wd
// slices -> L2 dedup. Double-buffered smem: 1 barrier per 16-k chunk.
__global__ __launch_bounds__(256, 2) void gemmF(const float* __restrict__ hs,
                                                const float* __restrict__ B,
                                                const float* __restrict__ bias) {
    __shared__ float As[2][16][64];
    __shared__ float Bs[2][16][256];
    __shared__ float red[8][8];
    const int t = blockIdx.x;
    const float* A = hs + (size_t)(t + 1) * NB * NH;
    const int tid = threadIdx.x;
    const int rowg = tid >> 6;        // 0..3  (16 rows each)
    const int colg = tid & 63;        // 0..63 (4 cols each)
    const int n0 = blockIdx.y * 256;
    const int w = tid >> 5, lane = tid & 31;
    const int ar = tid >> 2, ak = (tid & 3) * 4;
    const int bk = tid >> 4, bc = (tid & 15) * 16;

    unsigned long long acc[8][4];
#pragma unroll
    for (int p = 0; p < 8; p++)
#pragma unroll
        for (int c = 0; c < 4; c++) acc[p][c] = 0ull;

    // prolog: chunk0 -> buf0
    float4 pa = *(const float4*)(A + ar * NH + ak);
    float4 pb[4];
#pragma unroll
    for (int j = 0; j < 4; j++)
        pb[j] = *(const float4*)(B + (size_t)bk * NV + n0 + bc + j * 4);
    As[0][ak + 0][ar] = pa.x; As[0][ak + 1][ar] = pa.y;
    As[0][ak + 2][ar] = pa.z; As[0][ak + 3][ar] = pa.w;
#pragma unroll
    for (int j = 0; j < 4; j++)
        *(float4*)&Bs[0][bk][bc + j * 4] = pb[j];
    __syncthreads();

    for (int c = 0; c < 64; c++) {
        int cur = c & 1;
        if (c + 1 < 64) {   // issue LDG for chunk c+1
            pa = *(const float4*)(A + ar * NH + (c + 1) * 16 + ak);
#pragma unroll
            for (int j = 0; j < 4; j++)
                pb[j] = *(const float4*)(B + (size_t)((c + 1) * 16 + bk) * NV + n0 + bc + j * 4);
        }
#pragma unroll
        for (int k = 0; k < 16; k++) {
            ulonglong2 pAB = *(const ulonglong2*)&As[cur][k][rowg * 16];
            ulonglong2 pCD = *(const ulonglong2*)&As[cur][k][rowg * 16 + 4];
            ulonglong2 pEF = *(const ulonglong2*)&As[cur][k][rowg * 16 + 8];
            ulonglong2 pGH = *(const ulonglong2*)&As[cur][k][rowg * 16 + 12];
            float4 bv = *(const float4*)&Bs[cur][k][colg * 4];
            unsigned long long b0 = pk2(bv.x), b1 = pk2(bv.y);
            unsigned long long b2 = pk2(bv.z), b3 = pk2(bv.w);
            fma2(acc[0][0], pAB.x, b0); fma2(acc[0][1], pAB.x, b1);
            fma2(acc[0][2], pAB.x, b2); fma2(acc[0][3], pAB.x, b3);
            fma2(acc[1][0], pAB.y, b0); fma2(acc[1][1], pAB.y, b1);
            fma2(acc[1][2], pAB.y, b2); fma2(acc[1][3], pAB.y, b3);
            fma2(acc[2][0], pCD.x, b0); fma2(acc[2][1], pCD.x, b1);
            fma2(acc[2][2], pCD.x, b2); fma2(acc[2][3], pCD.x, b3);
            fma2(acc[3][0], pCD.y, b0); fma2(acc[3][1], pCD.y, b1);
            fma2(acc[3][2], pCD.y, b2); fma2(acc[3][3], pCD.y, b3);
            fma2(acc[4][0], pEF.x, b0); fma2(acc[4][1], pEF.x, b1);
            fma2(acc[4][2], pEF.x, b2); fma2(acc[4][3], pEF.x, b3);
            fma2(acc[5][0], pEF.y, b0); fma2(acc[5][1], pEF.y, b1);
            fma2(acc[5][2], pEF.y, b2); fma2(acc[5][3], pEF.y, b3);
            fma2(acc[6][0], pGH.x, b0); fma2(acc[6][1], pGH.x, b1);
            fma2(acc[6][2], pGH.x, b2); fma2(acc[6][3], pGH.x, b3);
            fma2(acc[7][0], pGH.y, b0); fma2(acc[7][1], pGH.y, b1);
            fma2(acc[7][2], pGH.y, b2); fma2(acc[7][3], pGH.y, b3);
        }
        if (c + 1 < 64) {   // store chunk c+1 -> other buffer
            As[cur ^ 1][ak + 0][ar] = pa.x; As[cur ^ 1][ak + 1][ar] = pa.y;
            As[cur ^ 1][ak + 2][ar] = pa.z; As[cur ^ 1][ak + 3][ar] = pa.w;
#pragma unroll
            for (int j = 0; j < 4; j++)
                *(float4*)&Bs[cur ^ 1][bk][bc + j * 4] = pb[j];
        }
        __syncthreads();
    }

    // ---- epilogue: softmax partials + two-pass gumbel argmax (unchanged) ----
    float bcol[4];
#pragma unroll
    for (int c = 0; c < 4; c++) bcol[c] = bias[n0 + colg * 4 + c];
    uint32_t kk0, kk1;
    tf2x32(0u, 1234u, 0u, (uint32_t)t, kk0, kk1);   // fold_in(key(1234), t)

    for (int i = 0; i < 16; i++) {
        int p = i >> 1;
        int rowAbs = rowg * 16 + i;
        float m = negInf(), S = 0.f, T = 0.f;

        // pass A: approx scores (tail exact), thread-local row max
        float ll[4], uu[4], sv[4];
        uint32_t approxMask = 0;
        float rb = negInf();
#pragma unroll
        for (int c = 0; c < 4; c++) {
            float l = __fadd_rn((i & 1) ? hi32(acc[p][c]) : lo32(acc[p][c]), bcol[c]);
            ll[c] = l;
            if (S == 0.f) { m = l; S = 1.f; T = 0.f; }
            else if (l > m) {
                float e = expf(m - l);
                T = (T + (m - l) * S) * e;
                S = S * e + 1.f;
                m = l;
            } else {
                float d = l - m, e = expf(d);
                S += e; T += d * e;
            }
            int v = n0 + colg * 4 + c;
            uint32_t o0, o1;
            tf2x32(kk0, kk1, 0u, (uint32_t)(rowAbs * NV + v), o0, o1);
            float u = u01(o0 ^ o1);
            uu[c] = u;
            float af = -__logf(u);
            float s;
            if (af < 1e-4f) {
                s = __fadd_rn(l, exact_g(u));       // exact now (tail, likely winner)
            } else {
                s = l - __logf(af);                 // fast approx
                approxMask |= (1u << c);
            }
            sv[c] = s;
            rb = fmaxf(rb, s);
        }
        for (int o = 16; o; o >>= 1)
            rb = fmaxf(rb, __shfl_xor_sync(0xffffffffu, rb, o));
        if (lane == 0) red[w][6] = rb;
        __syncthreads();
        rb = fmaxf(rb, red[w ^ 1][6]);
        float thresh = rb - 4e-3f;

        // pass B: exact-evaluate only margin survivors
        float best = negInf(), bl = 0.f;
        int bidx = 0x7fffffff;
#pragma unroll
        for (int c = 0; c < 4; c++) {
            float s;
            if (approxMask & (1u << c)) {
                if (sv[c] < thresh) continue;
                s = __fadd_rn(ll[c], exact_g(uu[c]));
            } else {
                s = sv[c];
                if (s < thresh) continue;
            }
            int v = n0 + colg * 4 + c;
            if (s > best || (s == best && v < bidx)) { best = s; bidx = v; bl = ll[c]; }
        }
        for (int o = 16; o; o >>= 1) {
            float m2 = __shfl_down_sync(0xffffffffu, m, o);
            float S2 = __shfl_down_sync(0xffffffffu, S, o);
            float T2 = __shfl_down_sync(0xffffffffu, T, o);
            softmerge(m, S, T, m2, S2, T2);
            float v2 = __shfl_down_sync(0xffffffffu, best, o);
            int   i2 = __shfl_down_sync(0xffffffffu, bidx, o);
            float l2 = __shfl_down_sync(0xffffffffu, bl, o);
            if (v2 > best || (v2 == best && i2 < bidx)) { best = v2; bidx = i2; bl = l2; }
        }
        __syncthreads();
        if (lane == 0) {
            red[w][0] = m; red[w][1] = S; red[w][2] = T;
            red[w][3] = best; red[w][4] = __int_as_float(bidx); red[w][5] = bl;
        }
        __syncthreads();
        if ((w & 1) == 0 && lane == 0) {
            softmerge(m, S, T, red[w + 1][0], red[w + 1][1], red[w + 1][2]);
            float v2 = red[w + 1][3]; int i2 = __float_as_int(red[w + 1][4]);
            float l2 = red[w + 1][5];
            if (v2 > best || (v2 == best && i2 < bidx)) { best = v2; bidx = i2; bl = l2; }
            int o = (t * NBLK + blockIdx.y) * NB + rowAbs;
            g_pm[o] = make_float4(m, S, T, 0.f);
            g_pa[o] = make_float4(best, (float)bidx, bl, 0.f);
        }
        __syncthreads();
    }
}

// Final merge over the 125 block partials, all 31 steps at once.
__global__ void k_fin(float* __restrict__ out) {
    int t = blockIdx.x;
    int tid = threadIdx.x, w = tid >> 5, lane = tid & 31;
    for (int row = w; row < NB; row += 8) {
        float m = negInf(), S = 0.f, T = 0.f;
        float best = negInf(), bl = 0.f;
        int bidx = 0x7fffffff;
        for (int b = lane; b < NBLK; b += 32) {
            int o = (t * NBLK + b) * NB + row;
            float4 pm = g_pm[o];
            softmerge(m, S, T, pm.x, pm.y, pm.z);
            float4 pa = g_pa[o];
            int i2 = (int)pa.y;
            if (pa.x > best || (pa.x == best && i2 < bidx)) {
                best = pa.x; bidx = i2; bl = pa.z;
            }
        }
        for (int o = 16; o; o >>= 1) {
            float m2 = __shfl_down_sync(0xffffffffu, m, o);
            float S2 = __shfl_down_sync(0xffffffffu, S, o);
            float T2 = __shfl_down_sync(0xffffffffu, T, o);
            softmerge(m, S, T, m2, S2, T2);
            float v2 = __shfl_down_sync(0xffffffffu, best, o);
            int   i2 = __shfl_down_sync(0xffffffffu, bidx, o);
            float l2 = __shfl_down_sync(0xffffffffu, bl, o);
            if (v2 > best || (v2 == best && i2 < bidx)) { best = v2; bidx = i2; bl = l2; }
        }
        if (lane == 0) {
            float lS = (float)log((double)S);
            out[2 * NB * 2 * NT + row * (2 * NT) + t] = lS - T / S;   // entropy
            out[row * (2 * NT) + t] = (float)bidx;                    // msg
            out[NB * 2 * NT + row * (2 * NT) + t] =
                __fadd_rn(__fadd_rn(bl, -m), -lS);                    // log_prob
        }
    }
}

__global__ void k_copyh(float* __restrict__ out, const float* __restrict__ h) {
    int i = blockIdx.x * blockDim.x + threadIdx.x;
    if (i < NB * NH) out[3 * NB * 2 * NT + i] = h[i];
}

extern "C" void kernel_launch(void* const* d_in, const int* in_sizes, int n_in,
                              void* d_out, int out_size) {
    // Size-based dispatch (robust to metadata ordering):
    const float *inp = 0, *Wx1 = 0, *Wd = 0, *bd = 0, *b1 = 0, *b2 = 0;
    const float* w4[3] = {0, 0, 0};
    int n4 = 0;
    for (int i = 0; i < n_in; i++) {
        const float* p = (const float*)d_in[i];
        switch (in_sizes[i]) {
            case 32768:    inp = p; break;
            case 2097152:  Wx1 = p; break;
            case 4194304:  if (n4 < 3) w4[n4++] = p; break;   // Wh1(unused), Wx2, Wh2
            case 32768000: Wd = p; break;
            case 32000:    bd = p; break;
            case 4096:     if (!b1) b1 = p; else b2 = p; break;
            default: break;
        }
    }
    float* out = (float*)d_out;

    void *pw1, *pw2, *phs;
    cudaGetSymbolAddress(&pw1, g_W1p);
    cudaGetSymbolAddress(&pw2, g_W2p);
    cudaGetSymbolAddress(&phs, g_hs);
    float* W1p = (float*)pw1;
    float* W2p = (float*)pw2;
    float* hs  = (float*)phs;

    k_init<<<256, 256>>>();
    k_init2<<<48, 256>>>(out);
    k_prep<<<16384, 256>>>(Wx1, w4[1], w4[2]);

    // encoder: one step, zero state -> hs[0]
    gemmG<<<256, 256>>>(inp, W1p, b1, hs, 512);

    // decoder state chain (the only sequential dependency)
    for (int t = 0; t < NT; t++)
        gemmG<<<256, 256>>>(hs + (size_t)t * NB * NH, W2p, b2,
                            hs + (size_t)(t + 1) * NB * NH, NH);

    // all 31 logits+sampling GEMMs in one wave-parallel launch
    gemmF<<<dim3(NT, NBLK), 256>>>(hs, Wd, bd);

    k_fin<<<NT, 256>>>(out);
    k_copyh<<<256, 256>>>(out, hs + (size_t)NT * NB * NH);
}

// round 12
// speedup vs baseline: 1.0933x; 1.0933x over previous
#include <cuda_runtime.h>
#include <stdint.h>
#include <math.h>

#define NB 64
#define NH 1024
#define NV 32000
#define NT 31
#define NBLK 250   // gemmF n-slices (32000/128)

// -------- device scratch --------
__device__ float g_W1p[512 * 4096];     // gate-interleaved Wx1
__device__ float g_W2p[1024 * 4096];    // gate-interleaved Wx2+Wh2
__device__ float g_hs[(NT + 1) * NB * NH];  // h after encoder (hs[0]) and each decoder step
__device__ float g_c[NB * NH];
__device__ float4 g_pm[NT * NBLK * NB];    // per-block softmax partials (m,S,T)
__device__ float4 g_pa[NT * NBLK * NB];    // per-block argmax partials (best, idx, l)

__device__ __forceinline__ float negInf() { return __int_as_float(0xff800000); }

// ---- packed f32x2 FMA (sm_103a): two independent rn-FMAs per instruction ----
__device__ __forceinline__ unsigned long long pk2(float x) {
    unsigned long long r;
    asm("mov.b64 %0, {%1, %1};" : "=l"(r) : "f"(x));
    return r;
}
__device__ __forceinline__ void fma2(unsigned long long& c, unsigned long long a,
                                     unsigned long long b) {
    asm("fma.rn.f32x2 %0, %1, %2, %0;" : "+l"(c) : "l"(a), "l"(b));
}
__device__ __forceinline__ float lo32(unsigned long long v) {
    return __uint_as_float((unsigned)v);
}
__device__ __forceinline__ float hi32(unsigned long long v) {
    return __uint_as_float((unsigned)(v >> 32));
}

// exact JAX threefry2x32 (20 rounds)
__device__ __forceinline__ void tf2x32(uint32_t k0, uint32_t k1,
                                       uint32_t x0, uint32_t x1,
                                       uint32_t& o0, uint32_t& o1) {
    uint32_t k2 = k0 ^ k1 ^ 0x1BD11BDAu;
    x0 += k0; x1 += k1;
#define TFR(r) { x0 += x1; x1 = (x1 << (r)) | (x1 >> (32 - (r))); x1 ^= x0; }
    TFR(13) TFR(15) TFR(26) TFR(6)
    x0 += k1; x1 += k2 + 1u;
    TFR(17) TFR(29) TFR(16) TFR(24)
    x0 += k2; x1 += k0 + 2u;
    TFR(13) TFR(15) TFR(26) TFR(6)
    x0 += k0; x1 += k1 + 3u;
    TFR(17) TFR(29) TFR(16) TFR(24)
    x0 += k1; x1 += k2 + 4u;
    TFR(13) TFR(15) TFR(26) TFR(6)
    x0 += k2; x1 += k0 + 5u;
#undef TFR
    o0 = x0; o1 = x1;
}

__device__ __forceinline__ float u01(uint32_t b) {
    float f = __uint_as_float((b >> 9) | 0x3f800000u) - 1.0f;
    return fmaxf(f, 1.17549435e-38f);
}

// exact gumbel increment (bit-identical to R6..R10 formula)
__device__ __forceinline__ float exact_g(float u) {
    return (float)(-log(-log((double)u)));
}

__device__ __forceinline__ void softmerge(float& m, float& S, float& T,
                                          float m2, float S2, float T2) {
    if (S2 == 0.f) return;
    if (S == 0.f) { m = m2; S = S2; T = T2; return; }
    if (m2 > m) {
        float t;
        t = m; m = m2; m2 = t;
        t = S; S = S2; S2 = t;
        t = T; T = T2; T2 = t;
    }
    float e = expf(m2 - m);
    S += S2 * e;
    T += (T2 + (m2 - m) * S2) * e;
}

__global__ void k_init() {
    int i = blockIdx.x * blockDim.x + threadIdx.x;
    if (i < NB * NH) g_c[i] = 0.f;
}
__global__ void k_init2(float* __restrict__ out) {
    int i = blockIdx.x * blockDim.x + threadIdx.x;
    if (i < 3 * NB * 2 * NT) out[i] = 0.f;
}

// Gate-interleave permutation: Wp[k][4j+q] = W[k][q*1024+j]
__global__ void k_prep(const float* __restrict__ Wx1, const float* __restrict__ Wx2,
                       const float* __restrict__ Wh2) {
    int idx = blockIdx.x * blockDim.x + threadIdx.x;   // < 1024*4096
    int k = idx >> 12, col = idx & 4095;
    int j = col >> 2, q = col & 3;
    int src = (k << 12) + (q << 10) + j;
    g_W2p[idx] = Wx2[src] + Wh2[src];
    if (k < 512) g_W1p[idx] = Wx1[src];
}

// Fused gate GEMM + LSTM pointwise. Double-buffered smem + depth-2 register
// prefetch. One cell per thread (aif, ago packed). (R11-measured: 30.1us)
__global__ __launch_bounds__(256, 2) void gemmG(const float* __restrict__ A,
                                                const float* __restrict__ W,
                                                const float* __restrict__ bias,
                                                float* __restrict__ hout,
                                                int K) {
    __shared__ float As[2][16][64];
    __shared__ float Bs[2][16][16];
    const int tid = threadIdx.x;
    const int row = tid & 63;
    const int jj  = tid >> 6;              // 0..3
    const int j0  = blockIdx.x * 4;        // 4 j-states per block
    const int c0  = blockIdx.x * 16;       // 16 permuted cols per block
    const int ar = tid >> 2, ak = (tid & 3) * 4;
    const int bk = tid >> 2, bc = (tid & 3) * 4;   // B staging (tid < 64)
    const int NC = K / 16;

    unsigned long long aif = 0, ago = 0;

    float4 pa0 = *(const float4*)(A + ar * K + ak);
    float4 pa1 = *(const float4*)(A + ar * K + 16 + ak);
    float4 pb0, pb1;
    if (tid < 64) {
        pb0 = *(const float4*)(W + (size_t)bk * 4096 + c0 + bc);
        pb1 = *(const float4*)(W + (size_t)(16 + bk) * 4096 + c0 + bc);
    }
    As[0][ak + 0][ar] = pa0.x; As[0][ak + 1][ar] = pa0.y;
    As[0][ak + 2][ar] = pa0.z; As[0][ak + 3][ar] = pa0.w;
    if (tid < 64) *(float4*)&Bs[0][bk][bc] = pb0;
    __syncthreads();
    pa0 = pa1;
    if (tid < 64) pb0 = pb1;

    for (int c = 0; c < NC; c++) {
        int cur = c & 1;
        if (c + 2 < NC) {
            pa1 = *(const float4*)(A + ar * K + (c + 2) * 16 + ak);
            if (tid < 64)
                pb1 = *(const float4*)(W + (size_t)((c + 2) * 16 + bk) * 4096 + c0 + bc);
        }
#pragma unroll
        for (int k = 0; k < 16; k++) {
            unsigned long long ap = pk2(As[cur][k][row]);
            ulonglong2 bA = *(const ulonglong2*)&Bs[cur][k][jj * 4];
            fma2(aif, ap, bA.x);
            fma2(ago, ap, bA.y);
        }
        if (c + 1 < NC) {
            As[cur ^ 1][ak + 0][ar] = pa0.x; As[cur ^ 1][ak + 1][ar] = pa0.y;
            As[cur ^ 1][ak + 2][ar] = pa0.z; As[cur ^ 1][ak + 3][ar] = pa0.w;
            if (tid < 64) *(float4*)&Bs[cur ^ 1][bk][bc] = pb0;
        }
        __syncthreads();
        pa0 = pa1;
        if (tid < 64) pb0 = pb1;
    }

    int j = j0 + jj;
    float zi = __fadd_rn(lo32(aif), bias[j]);
    float zf = __fadd_rn(hi32(aif), bias[1024 + j]);
    float zg = __fadd_rn(lo32(ago), bias[2048 + j]);
    float zo = __fadd_rn(hi32(ago), bias[3072 + j]);
    float si = 1.f / (1.f + expf(-zi));
    float sf = 1.f / (1.f + expf(-zf));
    float so = 1.f / (1.f + expf(-zo));
    int ci = row * NH + j;
    float cn = __fadd_rn(__fmul_rn(sf, g_c[ci]), __fmul_rn(si, zg));
    g_c[ci] = cn;
    hout[ci] = __fmul_rn(so, cn);
}

// ALL 31 steps' logits GEMM + softmax partials + gumbel sampling.
// Tile 64x128, 3 blocks/SM (6 warps/SMSP). Each warp owns 8 FULL rows
// (32 lanes x 4 cols = 128 cols) -> barrier-free epilogue (pure shfl).
// K-order per element identical to R10 -> logits bit-identical.
__global__ __launch_bounds__(256, 3) void gemmF(const float* __restrict__ hs,
                                                const float* __restrict__ B,
                                                const float* __restrict__ bias) {
    __shared__ float As[16][64];
    __shared__ float Bs[16][128];
    const int t = blockIdx.x;
    const float* A = hs + (size_t)(t + 1) * NB * NH;
    const int tid = threadIdx.x;
    const int rowg8 = (tid >> 5) * 8;  // warp owns rows rowg8..rowg8+7
    const int colg = tid & 31;         // lane owns cols colg*4..+3
    const int n0 = blockIdx.y * 128;
    const int lane = colg;
    const int ar = tid >> 2, ak = (tid & 3) * 4;
    const int bk = tid >> 4, bc = (tid & 15) * 8;

    unsigned long long acc[4][4];   // [row-pair][col]
#pragma unroll
    for (int p = 0; p < 4; p++)
#pragma unroll
        for (int c = 0; c < 4; c++) acc[p][c] = 0ull;

    // prolog: load chunk 0 into regs
    float4 pa = *(const float4*)(A + ar * NH + ak);
    float4 pb0 = *(const float4*)(B + (size_t)bk * NV + n0 + bc);
    float4 pb1 = *(const float4*)(B + (size_t)bk * NV + n0 + bc + 4);

    for (int c = 0; c < 64; c++) {
        As[ak + 0][ar] = pa.x; As[ak + 1][ar] = pa.y;
        As[ak + 2][ar] = pa.z; As[ak + 3][ar] = pa.w;
        *(float4*)&Bs[bk][bc] = pb0;
        *(float4*)&Bs[bk][bc + 4] = pb1;
        __syncthreads();
        if (c + 1 < 64) {
            pa = *(const float4*)(A + ar * NH + (c + 1) * 16 + ak);
            pb0 = *(const float4*)(B + (size_t)((c + 1) * 16 + bk) * NV + n0 + bc);
            pb1 = *(const float4*)(B + (size_t)((c + 1) * 16 + bk) * NV + n0 + bc + 4);
        }
#pragma unroll
        for (int k = 0; k < 16; k++) {
            ulonglong2 a01 = *(const ulonglong2*)&As[k][rowg8];
            ulonglong2 a23 = *(const ulonglong2*)&As[k][rowg8 + 4];
            float4 bv = *(const float4*)&Bs[k][colg * 4];
            unsigned long long b0 = pk2(bv.x), b1 = pk2(bv.y);
            unsigned long long b2 = pk2(bv.z), b3 = pk2(bv.w);
            fma2(acc[0][0], a01.x, b0); fma2(acc[0][1], a01.x, b1);
            fma2(acc[0][2], a01.x, b2); fma2(acc[0][3], a01.x, b3);
            fma2(acc[1][0], a01.y, b0); fma2(acc[1][1], a01.y, b1);
            fma2(acc[1][2], a01.y, b2); fma2(acc[1][3], a01.y, b3);
            fma2(acc[2][0], a23.x, b0); fma2(acc[2][1], a23.x, b1);
            fma2(acc[2][2], a23.x, b2); fma2(acc[2][3], a23.x, b3);
            fma2(acc[3][0], a23.y, b0); fma2(acc[3][1], a23.y, b1);
            fma2(acc[3][2], a23.y, b2); fma2(acc[3][3], a23.y, b3);
        }
        __syncthreads();
    }

    // ---- barrier-free epilogue: warp-complete rows ----
    float bcol[4];
#pragma unroll
    for (int c = 0; c < 4; c++) bcol[c] = bias[n0 + colg * 4 + c];
    uint32_t kk0, kk1;
    tf2x32(0u, 1234u, 0u, (uint32_t)t, kk0, kk1);   // fold_in(key(1234), t)

    for (int i = 0; i < 8; i++) {
        int p = i >> 1;
        int rowAbs = rowg8 + i;
        float m = negInf(), S = 0.f, T = 0.f;

        // pass A: approx scores (tail exact), lane-local max
        float ll[4], uu[4], sv[4];
        uint32_t approxMask = 0;
        float rb = negInf();
#pragma unroll
        for (int c = 0; c < 4; c++) {
            float l = __fadd_rn((i & 1) ? hi32(acc[p][c]) : lo32(acc[p][c]), bcol[c]);
            ll[c] = l;
            if (S == 0.f) { m = l; S = 1.f; T = 0.f; }
            else if (l > m) {
                float e = expf(m - l);
                T = (T + (m - l) * S) * e;
                S = S * e + 1.f;
                m = l;
            } else {
                float d = l - m, e = expf(d);
                S += e; T += d * e;
            }
            int v = n0 + colg * 4 + c;
            uint32_t o0, o1;
            tf2x32(kk0, kk1, 0u, (uint32_t)(rowAbs * NV + v), o0, o1);
            float u = u01(o0 ^ o1);
            uu[c] = u;
            float af = -__logf(u);
            float s;
            if (af < 1e-4f) {
                s = __fadd_rn(l, exact_g(u));       // exact now (tail, likely winner)
            } else {
                s = l - __logf(af);                 // fast approx
                approxMask |= (1u << c);
            }
            sv[c] = s;
            rb = fmaxf(rb, s);
        }
        // full-row approx max via warp allreduce (32 lanes = whole row slice)
        for (int o = 16; o; o >>= 1)
            rb = fmaxf(rb, __shfl_xor_sync(0xffffffffu, rb, o));
        float thresh = rb - 4e-3f;

        // pass B: exact-evaluate only margin survivors
        float best = negInf(), bl = 0.f;
        int bidx = 0x7fffffff;
#pragma unroll
        for (int c = 0; c < 4; c++) {
            float s;
            if (approxMask & (1u << c)) {
                if (sv[c] < thresh) continue;
                s = __fadd_rn(ll[c], exact_g(uu[c]));
            } else {
                s = sv[c];
                if (s < thresh) continue;
            }
            int v = n0 + colg * 4 + c;
            if (s > best || (s == best && v < bidx)) { best = s; bidx = v; bl = ll[c]; }
        }
        for (int o = 16; o; o >>= 1) {
            float m2 = __shfl_down_sync(0xffffffffu, m, o);
            float S2 = __shfl_down_sync(0xffffffffu, S, o);
            float T2 = __shfl_down_sync(0xffffffffu, T, o);
            softmerge(m, S, T, m2, S2, T2);
            float v2 = __shfl_down_sync(0xffffffffu, best, o);
            int   i2 = __shfl_down_sync(0xffffffffu, bidx, o);
            float l2 = __shfl_down_sync(0xffffffffu, bl, o);
            if (v2 > best || (v2 == best && i2 < bidx)) { best = v2; bidx = i2; bl = l2; }
        }
        if (lane == 0) {
            int o = (t * NBLK + blockIdx.y) * NB + rowAbs;
            g_pm[o] = make_float4(m, S, T, 0.f);
            g_pa[o] = make_float4(best, (float)bidx, bl, 0.f);
        }
    }
}

// Final merge over the 250 block partials, all 31 steps at once.
__global__ void k_fin(float* __restrict__ out) {
    int t = blockIdx.x;
    int tid = threadIdx.x, w = tid >> 5, lane = tid & 31;
    for (int row = w; row < NB; row += 8) {
        float m = negInf(), S = 0.f, T = 0.f;
        float best = negInf(), bl = 0.f;
        int bidx = 0x7fffffff;
        for (int b = lane; b < NBLK; b += 32) {
            int o = (t * NBLK + b) * NB + row;
            float4 pm = g_pm[o];
            softmerge(m, S, T, pm.x, pm.y, pm.z);
            float4 pa = g_pa[o];
            int i2 = (int)pa.y;
            if (pa.x > best || (pa.x == best && i2 < bidx)) {
                best = pa.x; bidx = i2; bl = pa.z;
            }
        }
        for (int o = 16; o; o >>= 1) {
            float m2 = __shfl_down_sync(0xffffffffu, m, o);
            float S2 = __shfl_down_sync(0xffffffffu, S, o);
            float T2 = __shfl_down_sync(0xffffffffu, T, o);
            softmerge(m, S, T, m2, S2, T2);
            float v2 = __shfl_down_sync(0xffffffffu, best, o);
            int   i2 = __shfl_down_sync(0xffffffffu, bidx, o);
            float l2 = __shfl_down_sync(0xffffffffu, bl, o);
            if (v2 > best || (v2 == best && i2 < bidx)) { best = v2; bidx = i2; bl = l2; }
        }
        if (lane == 0) {
            float lS = (float)log((double)S);
            out[2 * NB * 2 * NT + row * (2 * NT) + t] = lS - T / S;   // entropy
            out[row * (2 * NT) + t] = (float)bidx;                    // msg
            out[NB * 2 * NT + row * (2 * NT) + t] =
                __fadd_rn(__fadd_rn(bl, -m), -lS);                    // log_prob
        }
    }
}

__global__ void k_copyh(float* __restrict__ out, const float* __restrict__ h) {
    int i = blockIdx.x * blockDim.x + threadIdx.x;
    if (i < NB * NH) out[3 * NB * 2 * NT + i] = h[i];
}

extern "C" void kernel_launch(void* const* d_in, const int* in_sizes, int n_in,
                              void* d_out, int out_size) {
    // Size-based dispatch (robust to metadata ordering):
    const float *inp = 0, *Wx1 = 0, *Wd = 0, *bd = 0, *b1 = 0, *b2 = 0;
    const float* w4[3] = {0, 0, 0};
    int n4 = 0;
    for (int i = 0; i < n_in; i++) {
        const float* p = (const float*)d_in[i];
        switch (in_sizes[i]) {
            case 32768:    inp = p; break;
            case 2097152:  Wx1 = p; break;
            case 4194304:  if (n4 < 3) w4[n4++] = p; break;   // Wh1(unused), Wx2, Wh2
            case 32768000: Wd = p; break;
            case 32000:    bd = p; break;
            case 4096:     if (!b1) b1 = p; else b2 = p; break;
            default: break;
        }
    }
    float* out = (float*)d_out;

    void *pw1, *pw2, *phs;
    cudaGetSymbolAddress(&pw1, g_W1p);
    cudaGetSymbolAddress(&pw2, g_W2p);
    cudaGetSymbolAddress(&phs, g_hs);
    float* W1p = (float*)pw1;
    float* W2p = (float*)pw2;
    float* hs  = (float*)phs;

    k_init<<<256, 256>>>();
    k_init2<<<48, 256>>>(out);
    k_prep<<<16384, 256>>>(Wx1, w4[1], w4[2]);

    // encoder: one step, zero state -> hs[0]
    gemmG<<<256, 256>>>(inp, W1p, b1, hs, 512);

    // decoder state chain (the only sequential dependency)
    for (int t = 0; t < NT; t++)
        gemmG<<<256, 256>>>(hs + (size_t)t * NB * NH, W2p, b2,
                            hs + (size_t)(t + 1) * NB * NH, NH);

    // all 31 logits+sampling GEMMs in one wave-parallel launch
    gemmF<<<dim3(NT, NBLK), 256>>>(hs, Wd, bd);

    k_fin<<<NT, 256>>>(out);
    k_copyh<<<256, 256>>>(out, hs + (size_t)NT * NB * NH);
}

// round 13
// speedup vs baseline: 1.1379x; 1.0408x over previous
#include <cuda_runtime.h>
#include <stdint.h>
#include <math.h>

#define NB 64
#define NH 1024
#define NV 32000
#define NT 31
#define NBLK 250   // gemmF n-slices (32000/128)

// -------- device scratch --------
__device__ float g_W1p[512 * 4096];     // gate-interleaved Wx1
__device__ float g_W2p[1024 * 4096];    // gate-interleaved Wx2+Wh2
__device__ float g_hs[(NT + 1) * NB * NH];  // h after encoder (hs[0]) and each decoder step
__device__ float g_c[NB * NH];
__device__ float4 g_pm[NT * NBLK * NB];    // per-block softmax partials (m,S,T)
__device__ float4 g_pa[NT * NBLK * NB];    // per-block argmax partials (best, idx, l)

__device__ __forceinline__ float negInf() { return __int_as_float(0xff800000); }

// ---- packed f32x2 FMA (sm_103a): two independent rn-FMAs per instruction ----
__device__ __forceinline__ unsigned long long pk2(float x) {
    unsigned long long r;
    asm("mov.b64 %0, {%1, %1};" : "=l"(r) : "f"(x));
    return r;
}
__device__ __forceinline__ void fma2(unsigned long long& c, unsigned long long a,
                                     unsigned long long b) {
    asm("fma.rn.f32x2 %0, %1, %2, %0;" : "+l"(c) : "l"(a), "l"(b));
}
__device__ __forceinline__ float lo32(unsigned long long v) {
    return __uint_as_float((unsigned)v);
}
__device__ __forceinline__ float hi32(unsigned long long v) {
    return __uint_as_float((unsigned)(v >> 32));
}

// ---- cp.async (LDGSTS): register-free global->shared pipeline ----
#define CP16(dst, src) \
    asm volatile("cp.async.cg.shared.global [%0], [%1], 16;" :: "r"(dst), "l"(src))
#define CP4(dst, src) \
    asm volatile("cp.async.ca.shared.global [%0], [%1], 4;" :: "r"(dst), "l"(src))
#define CP_COMMIT() asm volatile("cp.async.commit_group;")
#define CP_WAIT2()  asm volatile("cp.async.wait_group 2;")

// exact JAX threefry2x32 (20 rounds)
__device__ __forceinline__ void tf2x32(uint32_t k0, uint32_t k1,
                                       uint32_t x0, uint32_t x1,
                                       uint32_t& o0, uint32_t& o1) {
    uint32_t k2 = k0 ^ k1 ^ 0x1BD11BDAu;
    x0 += k0; x1 += k1;
#define TFR(r) { x0 += x1; x1 = (x1 << (r)) | (x1 >> (32 - (r))); x1 ^= x0; }
    TFR(13) TFR(15) TFR(26) TFR(6)
    x0 += k1; x1 += k2 + 1u;
    TFR(17) TFR(29) TFR(16) TFR(24)
    x0 += k2; x1 += k0 + 2u;
    TFR(13) TFR(15) TFR(26) TFR(6)
    x0 += k0; x1 += k1 + 3u;
    TFR(17) TFR(29) TFR(16) TFR(24)
    x0 += k1; x1 += k2 + 4u;
    TFR(13) TFR(15) TFR(26) TFR(6)
    x0 += k2; x1 += k0 + 5u;
#undef TFR
    o0 = x0; o1 = x1;
}

__device__ __forceinline__ float u01(uint32_t b) {
    float f = __uint_as_float((b >> 9) | 0x3f800000u) - 1.0f;
    return fmaxf(f, 1.17549435e-38f);
}

// exact gumbel increment (bit-identical to R6..R12 formula)
__device__ __forceinline__ float exact_g(float u) {
    return (float)(-log(-log((double)u)));
}

__device__ __forceinline__ void softmerge(float& m, float& S, float& T,
                                          float m2, float S2, float T2) {
    if (S2 == 0.f) return;
    if (S == 0.f) { m = m2; S = S2; T = T2; return; }
    if (m2 > m) {
        float t;
        t = m; m = m2; m2 = t;
        t = S; S = S2; S2 = t;
        t = T; T = T2; T2 = t;
    }
    float e = expf(m2 - m);
    S += S2 * e;
    T += (T2 + (m2 - m) * S2) * e;
}

__global__ void k_init() {
    int i = blockIdx.x * blockDim.x + threadIdx.x;
    if (i < NB * NH) g_c[i] = 0.f;
}
__global__ void k_init2(float* __restrict__ out) {
    int i = blockIdx.x * blockDim.x + threadIdx.x;
    if (i < 3 * NB * 2 * NT) out[i] = 0.f;
}

// Gate-interleave permutation: Wp[k][4j+q] = W[k][q*1024+j]
__global__ void k_prep(const float* __restrict__ Wx1, const float* __restrict__ Wx2,
                       const float* __restrict__ Wh2) {
    int idx = blockIdx.x * blockDim.x + threadIdx.x;   // < 1024*4096
    int k = idx >> 12, col = idx & 4095;
    int j = col >> 2, q = col & 3;
    int src = (k << 12) + (q << 10) + j;
    g_W2p[idx] = Wx2[src] + Wh2[src];
    if (k < 512) g_W1p[idx] = Wx1[src];
}

// Fused gate GEMM + LSTM pointwise. B via 4-stage cp.async ring (all 256
// threads load), A via depth-2 register pipeline into double-buffered smem.
__global__ __launch_bounds__(256, 2) void gemmG(const float* __restrict__ A,
                                                const float* __restrict__ W,
                                                const float* __restrict__ bias,
                                                float* __restrict__ hout,
                                                int K) {
    __shared__ float As[2][16][64];
    __shared__ float Bs[4][16][16];
    const int tid = threadIdx.x;
    const int row = tid & 63;
    const int jj  = tid >> 6;              // 0..3
    const int j0  = blockIdx.x * 4;        // 4 j-states per block
    const int c0  = blockIdx.x * 16;       // 16 permuted cols per block
    const int ar = tid >> 2, ak = (tid & 3) * 4;
    const int kr = tid >> 4, cc = tid & 15;     // B scalar staging (all threads)
    const int NC = K / 16;

    unsigned long long aif = 0, ago = 0;

    const float* bsrc = W + (size_t)kr * 4096 + c0 + cc;
    uint32_t bBase = (uint32_t)__cvta_generic_to_shared(&Bs[0][kr][cc]);

    // prolog: B stages 0..2 in flight; A chunk0 -> As[0], chunk1 in regs
#pragma unroll
    for (int s = 0; s < 3; s++) {
        if (s < NC) CP4(bBase + s * 1024, bsrc + (size_t)s * 16 * 4096);
        CP_COMMIT();
    }
    float4 paN;
    {
        float4 p0 = *(const float4*)(A + ar * K + ak);
        As[0][ak + 0][ar] = p0.x; As[0][ak + 1][ar] = p0.y;
        As[0][ak + 2][ar] = p0.z; As[0][ak + 3][ar] = p0.w;
        paN = *(const float4*)(A + ar * K + 16 + ak);
    }

    for (int c = 0; c < NC; c++) {
        CP_WAIT2();
        __syncthreads();
        if (c + 1 < NC) {
            int b = (c + 1) & 1;
            As[b][ak + 0][ar] = paN.x; As[b][ak + 1][ar] = paN.y;
            As[b][ak + 2][ar] = paN.z; As[b][ak + 3][ar] = paN.w;
        }
        if (c + 2 < NC) paN = *(const float4*)(A + ar * K + (c + 2) * 16 + ak);
        if (c + 3 < NC) CP4(bBase + ((c + 3) & 3) * 1024,
                            bsrc + (size_t)(c + 3) * 16 * 4096);
        CP_COMMIT();
        int cur = c & 1, cb = c & 3;
#pragma unroll
        for (int k = 0; k < 16; k++) {
            unsigned long long ap = pk2(As[cur][k][row]);
            ulonglong2 bA = *(const ulonglong2*)&Bs[cb][k][jj * 4];
            fma2(aif, ap, bA.x);
            fma2(ago, ap, bA.y);
        }
    }

    int j = j0 + jj;
    float zi = __fadd_rn(lo32(aif), bias[j]);
    float zf = __fadd_rn(hi32(aif), bias[1024 + j]);
    float zg = __fadd_rn(lo32(ago), bias[2048 + j]);
    float zo = __fadd_rn(hi32(ago), bias[3072 + j]);
    float si = 1.f / (1.f + expf(-zi));
    float sf = 1.f / (1.f + expf(-zf));
    float so = 1.f / (1.f + expf(-zo));
    int ci = row * NH + j;
    float cn = __fadd_rn(__fmul_rn(sf, g_c[ci]), __fmul_rn(si, zg));
    g_c[ci] = cn;
    hout[ci] = __fmul_rn(so, cn);
}

// ALL 31 steps' logits GEMM + softmax partials + gumbel sampling.
// Tile 64x128, 3 blocks/SM. B via 4-stage cp.async ring (3-chunk slack
// ~570cyc > L2 262), A depth-2 regs. Inner loop & k-order unchanged from
// R12 -> logits bit-identical. Barrier-free warp-complete-row epilogue.
__global__ __launch_bounds__(256, 3) void gemmF(const float* __restrict__ hs,
                                                const float* __restrict__ B,
                                                const float* __restrict__ bias) {
    __shared__ float As[2][16][64];
    __shared__ float Bs[4][16][128];
    const int t = blockIdx.x;
    const float* A = hs + (size_t)(t + 1) * NB * NH;
    const int tid = threadIdx.x;
    const int rowg8 = (tid >> 5) * 8;  // warp owns rows rowg8..rowg8+7
    const int colg = tid & 31;         // lane owns cols colg*4..+3
    const int n0 = blockIdx.y * 128;
    const int lane = colg;
    const int ar = tid >> 2, ak = (tid & 3) * 4;
    const int bk = tid >> 4, bc = (tid & 15) * 8;

    unsigned long long acc[4][4];   // [row-pair][col]
#pragma unroll
    for (int p = 0; p < 4; p++)
#pragma unroll
        for (int c = 0; c < 4; c++) acc[p][c] = 0ull;

    const float* bsrc = B + (size_t)bk * NV + n0 + bc;
    uint32_t bBase = (uint32_t)__cvta_generic_to_shared(&Bs[0][bk][bc]);

    // prolog: B stages 0..2; A chunk0 -> As[0], chunk1 in regs
#pragma unroll
    for (int s = 0; s < 3; s++) {
        CP16(bBase + s * 8192, bsrc + (size_t)s * 16 * NV);
        CP16(bBase + s * 8192 + 16, bsrc + (size_t)s * 16 * NV + 4);
        CP_COMMIT();
    }
    float4 paN;
    {
        float4 p0 = *(const float4*)(A + ar * NH + ak);
        As[0][ak + 0][ar] = p0.x; As[0][ak + 1][ar] = p0.y;
        As[0][ak + 2][ar] = p0.z; As[0][ak + 3][ar] = p0.w;
        paN = *(const float4*)(A + ar * NH + 16 + ak);
    }

    for (int c = 0; c < 64; c++) {
        CP_WAIT2();
        __syncthreads();
        if (c + 1 < 64) {
            int b = (c + 1) & 1;
            As[b][ak + 0][ar] = paN.x; As[b][ak + 1][ar] = paN.y;
            As[b][ak + 2][ar] = paN.z; As[b][ak + 3][ar] = paN.w;
        }
        if (c + 2 < 64) paN = *(const float4*)(A + ar * NH + (c + 2) * 16 + ak);
        if (c + 3 < 64) {
            uint32_t d = bBase + ((c + 3) & 3) * 8192;
            const float* s = bsrc + (size_t)(c + 3) * 16 * NV;
            CP16(d, s);
            CP16(d + 16, s + 4);
        }
        CP_COMMIT();
        int cur = c & 1, cb = c & 3;
#pragma unroll
        for (int k = 0; k < 16; k++) {
            ulonglong2 a01 = *(const ulonglong2*)&As[cur][k][rowg8];
            ulonglong2 a23 = *(const ulonglong2*)&As[cur][k][rowg8 + 4];
            float4 bv = *(const float4*)&Bs[cb][k][colg * 4];
            unsigned long long b0 = pk2(bv.x), b1 = pk2(bv.y);
            unsigned long long b2 = pk2(bv.z), b3 = pk2(bv.w);
            fma2(acc[0][0], a01.x, b0); fma2(acc[0][1], a01.x, b1);
            fma2(acc[0][2], a01.x, b2); fma2(acc[0][3], a01.x, b3);
            fma2(acc[1][0], a01.y, b0); fma2(acc[1][1], a01.y, b1);
            fma2(acc[1][2], a01.y, b2); fma2(acc[1][3], a01.y, b3);
            fma2(acc[2][0], a23.x, b0); fma2(acc[2][1], a23.x, b1);
            fma2(acc[2][2], a23.x, b2); fma2(acc[2][3], a23.x, b3);
            fma2(acc[3][0], a23.y, b0); fma2(acc[3][1], a23.y, b1);
            fma2(acc[3][2], a23.y, b2); fma2(acc[3][3], a23.y, b3);
        }
    }

    // ---- barrier-free epilogue: warp-complete rows (unchanged from R12) ----
    float bcol[4];
#pragma unroll
    for (int c = 0; c < 4; c++) bcol[c] = bias[n0 + colg * 4 + c];
    uint32_t kk0, kk1;
    tf2x32(0u, 1234u, 0u, (uint32_t)t, kk0, kk1);   // fold_in(key(1234), t)

    for (int i = 0; i < 8; i++) {
        int p = i >> 1;
        int rowAbs = rowg8 + i;
        float m = negInf(), S = 0.f, T = 0.f;

        // pass A: approx scores (tail exact), lane-local max
        float ll[4], uu[4], sv[4];
        uint32_t approxMask = 0;
        float rb = negInf();
#pragma unroll
        for (int c = 0; c < 4; c++) {
            float l = __fadd_rn((i & 1) ? hi32(acc[p][c]) : lo32(acc[p][c]), bcol[c]);
            ll[c] = l;
            if (S == 0.f) { m = l; S = 1.f; T = 0.f; }
            else if (l > m) {
                float e = expf(m - l);
                T = (T + (m - l) * S) * e;
                S = S * e + 1.f;
                m = l;
            } else {
                float d = l - m, e = expf(d);
                S += e; T += d * e;
            }
            int v = n0 + colg * 4 + c;
            uint32_t o0, o1;
            tf2x32(kk0, kk1, 0u, (uint32_t)(rowAbs * NV + v), o0, o1);
            float u = u01(o0 ^ o1);
            uu[c] = u;
            float af = -__logf(u);
            float s;
            if (af < 1e-4f) {
                s = __fadd_rn(l, exact_g(u));       // exact now (tail, likely winner)
            } else {
                s = l - __logf(af);                 // fast approx
                approxMask |= (1u << c);
            }
            sv[c] = s;
            rb = fmaxf(rb, s);
        }
        for (int o = 16; o; o >>= 1)
            rb = fmaxf(rb, __shfl_xor_sync(0xffffffffu, rb, o));
        float thresh = rb - 4e-3f;

        // pass B: exact-evaluate only margin survivors
        float best = negInf(), bl = 0.f;
        int bidx = 0x7fffffff;
#pragma unroll
        for (int c = 0; c < 4; c++) {
            float s;
            if (approxMask & (1u << c)) {
                if (sv[c] < thresh) continue;
                s = __fadd_rn(ll[c], exact_g(uu[c]));
            } else {
                s = sv[c];
                if (s < thresh) continue;
            }
            int v = n0 + colg * 4 + c;
            if (s > best || (s == best && v < bidx)) { best = s; bidx = v; bl = ll[c]; }
        }
        for (int o = 16; o; o >>= 1) {
            float m2 = __shfl_down_sync(0xffffffffu, m, o);
            float S2 = __shfl_down_sync(0xffffffffu, S, o);
            float T2 = __shfl_down_sync(0xffffffffu, T, o);
            softmerge(m, S, T, m2, S2, T2);
            float v2 = __shfl_down_sync(0xffffffffu, best, o);
            int   i2 = __shfl_down_sync(0xffffffffu, bidx, o);
            float l2 = __shfl_down_sync(0xffffffffu, bl, o);
            if (v2 > best || (v2 == best && i2 < bidx)) { best = v2; bidx = i2; bl = l2; }
        }
        if (lane == 0) {
            int o = (t * NBLK + blockIdx.y) * NB + rowAbs;
            g_pm[o] = make_float4(m, S, T, 0.f);
            g_pa[o] = make_float4(best, (float)bidx, bl, 0.f);
        }
    }
}

// Final merge over the 250 block partials, all 31 steps at once.
__global__ void k_fin(float* __restrict__ out) {
    int t = blockIdx.x;
    int tid = threadIdx.x, w = tid >> 5, lane = tid & 31;
    for (int row = w; row < NB; row += 8) {
        float m = negInf(), S = 0.f, T = 0.f;
        float best = negInf(), bl = 0.f;
        int bidx = 0x7fffffff;
        for (int b = lane; b < NBLK; b += 32) {
            int o = (t * NBLK + b) * NB + row;
            float4 pm = g_pm[o];
            softmerge(m, S, T, pm.x, pm.y, pm.z);
            float4 pa = g_pa[o];
            int i2 = (int)pa.y;
            if (pa.x > best || (pa.x == best && i2 < bidx)) {
                best = pa.x; bidx = i2; bl = pa.z;
            }
        }
        for (int o = 16; o; o >>= 1) {
            float m2 = __shfl_down_sync(0xffffffffu, m, o);
            float S2 = __shfl_down_sync(0xffffffffu, S, o);
            float T2 = __shfl_down_sync(0xffffffffu, T, o);
            softmerge(m, S, T, m2, S2, T2);
            float v2 = __shfl_down_sync(0xffffffffu, best, o);
            int   i2 = __shfl_down_sync(0xffffffffu, bidx, o);
            float l2 = __shfl_down_sync(0xffffffffu, bl, o);
            if (v2 > best || (v2 == best && i2 < bidx)) { best = v2; bidx = i2; bl = l2; }
        }
        if (lane == 0) {
            float lS = (float)log((double)S);
            out[2 * NB * 2 * NT + row * (2 * NT) + t] = lS - T / S;   // entropy
            out[row * (2 * NT) + t] = (float)bidx;                    // msg
            out[NB * 2 * NT + row * (2 * NT) + t] =
                __fadd_rn(__fadd_rn(bl, -m), -lS);                    // log_prob
        }
    }
}

__global__ void k_copyh(float* __restrict__ out, const float* __restrict__ h) {
    int i = blockIdx.x * blockDim.x + threadIdx.x;
    if (i < NB * NH) out[3 * NB * 2 * NT + i] = h[i];
}

extern "C" void kernel_launch(void* const* d_in, const int* in_sizes, int n_in,
                              void* d_out, int out_size) {
    // Size-based dispatch (robust to metadata ordering):
    const float *inp = 0, *Wx1 = 0, *Wd = 0, *bd = 0, *b1 = 0, *b2 = 0;
    const float* w4[3] = {0, 0, 0};
    int n4 = 0;
    for (int i = 0; i < n_in; i++) {
        const float* p = (const float*)d_in[i];
        switch (in_sizes[i]) {
            case 32768:    inp = p; break;
            case 2097152:  Wx1 = p; break;
            case 4194304:  if (n4 < 3) w4[n4++] = p; break;   // Wh1(unused), Wx2, Wh2
            case 32768000: Wd = p; break;
            case 32000:    bd = p; break;
            case 4096:     if (!b1) b1 = p; else b2 = p; break;
            default: break;
        }
    }
    float* out = (float*)d_out;

    void *pw1, *pw2, *phs;
    cudaGetSymbolAddress(&pw1, g_W1p);
    cudaGetSymbolAddress(&pw2, g_W2p);
    cudaGetSymbolAddress(&phs, g_hs);
    float* W1p = (float*)pw1;
    float* W2p = (float*)pw2;
    float* hs  = (float*)phs;

    k_init<<<256, 256>>>();
    k_init2<<<48, 256>>>(out);
    k_prep<<<16384, 256>>>(Wx1, w4[1], w4[2]);

    // encoder: one step, zero state -> hs[0]
    gemmG<<<256, 256>>>(inp, W1p, b1, hs, 512);

    // decoder state chain (the only sequential dependency)
    for (int t = 0; t < NT; t++)
        gemmG<<<256, 256>>>(hs + (size_t)t * NB * NH, W2p, b2,
                            hs + (size_t)(t + 1) * NB * NH, NH);

    // all 31 logits+sampling GEMMs in one wave-parallel launch
    gemmF<<<dim3(NT, NBLK), 256>>>(hs, Wd, bd);

    k_fin<<<NT, 256>>>(out);
    k_copyh<<<256, 256>>>(out, hs + (size_t)NT * NB * NH);
}